// round 16
// baseline (speedup 1.0000x reference)
#include <cuda_runtime.h>

// Loss_Antonymy: out = sum_i relu(1 + sign_i * tanh(||A1_i - S2_i||_2)),
// sign_i = -1 if labels[i]==2 else +1.
// N = 1048576, D = 64. Inputs: S2_out [N*64] f32, A1_out [N*64] f32, labels [N] int32.
// Output: 1 float.
//
// R16: R12 hot loop (kernel floor: 78.0-78.4us @ 87-88% DRAM = B300 LTS cap,
// reproduced 3x) with the zeroing kernel replaced by a cudaMemsetAsync graph
// memset node (cheaper dispatch than a 1-thread kernel node). Config:
//  - half-warp per row, float4 __ldg, unroll x2 (MLP=4), hoisted label loads
//  - regs pinned <=32 via __launch_bounds__(256,8)
//  - 1024 blocks = 8192 warps -> exactly 32 quads/warp (zero remainder)

#define D 64

__global__ __launch_bounds__(256, 8)
void loss_antonymy_kernel(const float* __restrict__ S2,
                          const float* __restrict__ A1,
                          const int* __restrict__ labels,
                          float* __restrict__ out,
                          int nrows)
{
    const int lane  = threadIdx.x & 31;
    const int half  = lane >> 4;        // 0 or 1: which row within a pair
    const int sub   = lane & 15;        // 16 float4 = 64 floats of one row
    const int gwarp = (blockIdx.x * blockDim.x + threadIdx.x) >> 5;
    const int nwarp = (gridDim.x * blockDim.x) >> 5;
    const int nquads = nrows >> 2;      // 4 rows per warp iteration

    float acc = 0.0f;

    for (int quad = gwarp; quad < nquads; quad += nwarp) {
        const long long row0 = (long long)quad * 4 + half;
        const long long row1 = row0 + 2;

        const float4* a0 = reinterpret_cast<const float4*>(A1 + row0 * D);
        const float4* s0 = reinterpret_cast<const float4*>(S2 + row0 * D);
        const float4* a1 = reinterpret_cast<const float4*>(A1 + row1 * D);
        const float4* s1 = reinterpret_cast<const float4*>(S2 + row1 * D);

        // front-batch all loads: 4 independent 16B vector loads + 2 broadcast
        // label words (scalar loads overlap the stream instead of serializing
        // after the shuffle chain)
        float4 av0 = __ldg(&a0[sub]);
        float4 sv0 = __ldg(&s0[sub]);
        float4 av1 = __ldg(&a1[sub]);
        float4 sv1 = __ldg(&s1[sub]);
        int    lb0 = __ldg(&labels[row0]);
        int    lb1 = __ldg(&labels[row1]);

        float dx0 = av0.x - sv0.x, dy0 = av0.y - sv0.y;
        float dz0 = av0.z - sv0.z, dw0 = av0.w - sv0.w;
        float ss0 = dx0*dx0 + dy0*dy0 + dz0*dz0 + dw0*dw0;

        float dx1 = av1.x - sv1.x, dy1 = av1.y - sv1.y;
        float dz1 = av1.z - sv1.z, dw1 = av1.w - sv1.w;
        float ss1 = dx1*dx1 + dy1*dy1 + dz1*dz1 + dw1*dw1;

        // reduce each across the 16 lanes of this half-warp
        #pragma unroll
        for (int o = 8; o > 0; o >>= 1) {
            ss0 += __shfl_xor_sync(0xffffffffu, ss0, o);
            ss1 += __shfl_xor_sync(0xffffffffu, ss1, o);
        }

        if (sub == 0) {
            float sign0 = (lb0 == 2) ? -1.0f : 1.0f;
            float sign1 = (lb1 == 2) ? -1.0f : 1.0f;
            acc += fmaxf(0.0f, fmaf(sign0, tanhf(sqrtf(ss0)), 1.0f));
            acc += fmaxf(0.0f, fmaf(sign1, tanhf(sqrtf(ss1)), 1.0f));
        }
    }

    // block reduction: intra-warp, then across warps via shared, one atomic per block
    #pragma unroll
    for (int o = 16; o > 0; o >>= 1)
        acc += __shfl_xor_sync(0xffffffffu, acc, o);

    __shared__ float wsum[8];   // 256 threads -> 8 warps
    const int wid = threadIdx.x >> 5;
    if (lane == 0) wsum[wid] = acc;
    __syncthreads();

    if (wid == 0) {
        float v = (lane < (blockDim.x >> 5)) ? wsum[lane] : 0.0f;
        #pragma unroll
        for (int o = 4; o > 0; o >>= 1)
            v += __shfl_xor_sync(0xffffffffu, v, o);
        if (lane == 0)
            atomicAdd(out, v);
    }
}

extern "C" void kernel_launch(void* const* d_in, const int* in_sizes, int n_in,
                              void* d_out, int out_size)
{
    const float* S2     = (const float*)d_in[0];
    const float* A1     = (const float*)d_in[1];
    const int*   labels = (const int*)d_in[2];
    float*       out    = (float*)d_out;

    const int nrows = in_sizes[2];   // labels element count = N

    // Zero the 4-byte accumulator via a graph memset node (async, capture-legal,
    // cheaper dispatch than a 1-thread kernel node).
    cudaMemsetAsync(out, 0, sizeof(float));

    // 1024 blocks = 8192 warps: 262144 quads / 8192 = exactly 32 iterations
    // per warp (zero remainder, clean drain); all blocks co-resident.
    loss_antonymy_kernel<<<1024, 256>>>(S2, A1, labels, out, nrows);
}

// round 17
// speedup vs baseline: 1.0004x; 1.0004x over previous
#include <cuda_runtime.h>

// Loss_Antonymy: out = sum_i relu(1 + sign_i * tanh(||A1_i - S2_i||_2)),
// sign_i = -1 if labels[i]==2 else +1.
// N = 1048576, D = 64. Inputs: S2_out [N*64] f32, A1_out [N*64] f32, labels [N] int32.
// Output: 1 float.
//
// FINAL. Kernel is pinned at the B300 LTS chip cap (~6300 B/cyc ≈ 6.9-7.0 TB/s
// path-independent): 516 MB single-pass -> 74.3us ideal + ~4us ramp/drain =
// 78.0-78.4us kernel, reproduced 3x at 87-88% DRAM. 16 rounds of controlled
// experiments found no structure below this floor; wall-time spread across
// epilogue/zeroing variants (kernel node / memset node / PDL / fused membar /
// fused scoped-atomic) is replay-timing noise (±1us), not structure.
// Configuration (each element individually validated):
//  - half-warp per row, float4 __ldg loads, unroll x2 (MLP=4/thread)
//  - label loads hoisted into the front load batch (broadcast, overlapped)
//  - regs pinned <=32 via __launch_bounds__(256,8) (ptxas sits at a 32-reg
//    cliff: any spill to >32 costs a wave — see R4/R6 regressions)
//  - 1024 blocks = 8192 warps -> exactly 32 quads/warp (zero remainder)
//  - separate 1-thread zero kernel (fused epilogues measured no better)

#define D 64

__global__ void zero_out_kernel(float* out) {
    out[0] = 0.0f;
}

__global__ __launch_bounds__(256, 8)
void loss_antonymy_kernel(const float* __restrict__ S2,
                          const float* __restrict__ A1,
                          const int* __restrict__ labels,
                          float* __restrict__ out,
                          int nrows)
{
    const int lane  = threadIdx.x & 31;
    const int half  = lane >> 4;        // 0 or 1: which row within a pair
    const int sub   = lane & 15;        // 16 float4 = 64 floats of one row
    const int gwarp = (blockIdx.x * blockDim.x + threadIdx.x) >> 5;
    const int nwarp = (gridDim.x * blockDim.x) >> 5;
    const int nquads = nrows >> 2;      // 4 rows per warp iteration

    float acc = 0.0f;

    for (int quad = gwarp; quad < nquads; quad += nwarp) {
        const long long row0 = (long long)quad * 4 + half;
        const long long row1 = row0 + 2;

        const float4* a0 = reinterpret_cast<const float4*>(A1 + row0 * D);
        const float4* s0 = reinterpret_cast<const float4*>(S2 + row0 * D);
        const float4* a1 = reinterpret_cast<const float4*>(A1 + row1 * D);
        const float4* s1 = reinterpret_cast<const float4*>(S2 + row1 * D);

        // front-batch all loads: 4 independent 16B vector loads + 2 broadcast
        // label words (scalar loads overlap the stream instead of serializing
        // after the shuffle chain)
        float4 av0 = __ldg(&a0[sub]);
        float4 sv0 = __ldg(&s0[sub]);
        float4 av1 = __ldg(&a1[sub]);
        float4 sv1 = __ldg(&s1[sub]);
        int    lb0 = __ldg(&labels[row0]);
        int    lb1 = __ldg(&labels[row1]);

        float dx0 = av0.x - sv0.x, dy0 = av0.y - sv0.y;
        float dz0 = av0.z - sv0.z, dw0 = av0.w - sv0.w;
        float ss0 = dx0*dx0 + dy0*dy0 + dz0*dz0 + dw0*dw0;

        float dx1 = av1.x - sv1.x, dy1 = av1.y - sv1.y;
        float dz1 = av1.z - sv1.z, dw1 = av1.w - sv1.w;
        float ss1 = dx1*dx1 + dy1*dy1 + dz1*dz1 + dw1*dw1;

        // reduce each across the 16 lanes of this half-warp
        #pragma unroll
        for (int o = 8; o > 0; o >>= 1) {
            ss0 += __shfl_xor_sync(0xffffffffu, ss0, o);
            ss1 += __shfl_xor_sync(0xffffffffu, ss1, o);
        }

        if (sub == 0) {
            float sign0 = (lb0 == 2) ? -1.0f : 1.0f;
            float sign1 = (lb1 == 2) ? -1.0f : 1.0f;
            acc += fmaxf(0.0f, fmaf(sign0, tanhf(sqrtf(ss0)), 1.0f));
            acc += fmaxf(0.0f, fmaf(sign1, tanhf(sqrtf(ss1)), 1.0f));
        }
    }

    // block reduction: intra-warp, then across warps via shared, one atomic per block
    #pragma unroll
    for (int o = 16; o > 0; o >>= 1)
        acc += __shfl_xor_sync(0xffffffffu, acc, o);

    __shared__ float wsum[8];   // 256 threads -> 8 warps
    const int wid = threadIdx.x >> 5;
    if (lane == 0) wsum[wid] = acc;
    __syncthreads();

    if (wid == 0) {
        float v = (lane < (blockDim.x >> 5)) ? wsum[lane] : 0.0f;
        #pragma unroll
        for (int o = 4; o > 0; o >>= 1)
            v += __shfl_xor_sync(0xffffffffu, v, o);
        if (lane == 0)
            atomicAdd(out, v);
    }
}

extern "C" void kernel_launch(void* const* d_in, const int* in_sizes, int n_in,
                              void* d_out, int out_size)
{
    const float* S2     = (const float*)d_in[0];
    const float* A1     = (const float*)d_in[1];
    const int*   labels = (const int*)d_in[2];
    float*       out    = (float*)d_out;

    const int nrows = in_sizes[2];   // labels element count = N

    zero_out_kernel<<<1, 1>>>(out);

    // 1024 blocks = 8192 warps: 262144 quads / 8192 = exactly 32 iterations
    // per warp (zero remainder, clean drain); all blocks co-resident.
    loss_antonymy_kernel<<<1024, 256>>>(S2, A1, labels, out, nrows);
}